// round 4
// baseline (speedup 1.0000x reference)
#include <cuda_runtime.h>
#include <cstdint>

#define TT 500000
#define AA 20000
#define GG 250000
#define TOTAL_U 1000000

// ---------------- scratch (device globals; zero-initialized at load) ----------
__device__ int   g_start[GG];
__device__ int   g_end[GG];
__device__ float g_max[GG];
__device__ float g_rsum[GG];

// ---------------- segment softmax (gate_id is sorted) -------------------------
__global__ void seg_bounds_kernel(const int* __restrict__ gid) {
    int i = blockIdx.x * blockDim.x + threadIdx.x;
    if (i >= TOTAL_U) return;
    int g = gid[i];
    if (i == 0 || gid[i - 1] != g) g_start[g] = i;
    if (i == TOTAL_U - 1 || gid[i + 1] != g) g_end[g] = i + 1;
}

__global__ void seg_reduce_kernel(const float* __restrict__ U) {
    int g = blockIdx.x * blockDim.x + threadIdx.x;
    if (g >= GG) return;
    int s = g_start[g], e = g_end[g];
    if (s >= e) return;  // empty gate: never read downstream
    float m = -3.402823e38f;
    for (int i = s; i < e; i++) m = fmaxf(m, U[i]);
    float sum = 0.f;
    for (int i = s; i < e; i++) sum += __expf(U[i] - m);
    g_max[g] = m;
    g_rsum[g] = __fdividef(1.f, sum);
}

__global__ void seg_norm_kernel(const float* __restrict__ U,
                                const int* __restrict__ gid,
                                float* __restrict__ w) {
    int i = blockIdx.x * blockDim.x + threadIdx.x;
    if (i >= TOTAL_U) return;
    int g = gid[i];
    w[i] = __expf(U[i] - g_max[g]) * g_rsum[g];
}

// ---------------- main timing-arc kernel --------------------------------------
// One thread per (t, k) arc-ref. Threads [0,T) handle k=0 (rise-arc column),
// threads [T,2T) handle k=1 (fall-arc column) -> coalesced arc index loads.
__global__ void __launch_bounds__(256)
arcs_kernel(const float* __restrict__ in_arr,   // [T,2]
            const float* __restrict__ in_slew,  // [T,2]
            const float* __restrict__ c1,       // [T]
            const float* __restrict__ c2,       // [T]
            const int*   __restrict__ arc_r,    // [T]
            const int*   __restrict__ arc_f,    // [T]
            const int*   __restrict__ unate,    // [A]
            const float* __restrict__ dtab,     // [A,8,8]
            const float* __restrict__ stab,     // [A,8,8]
            const float* __restrict__ sidx,     // [A,8]
            const float* __restrict__ lidx,     // [A,8]
            float* __restrict__ out)            // [T,4]
{
    int idx = blockIdx.x * blockDim.x + threadIdx.x;
    if (idx >= 2 * TT) return;
    int k = (idx >= TT) ? 1 : 0;
    int t = idx - k * TT;

    int arc = k ? arc_f[t] : arc_r[t];
    int rf  = unate[arc] ^ k;

    float x   = in_slew[2 * t + rf];   // selected input slew
    float arr = in_arr[2 * t + rf];    // selected input arrival
    float c1f = c1[t] * 1e-15f;        // / SCALE
    float c2f = c2[t] * 1e-15f;

    // ---- slew-axis interval (fixed for this thread) ----
    const float4* sp = (const float4*)(sidx + arc * 8);
    float4 sA = sp[0], sB = sp[1];
    float sax[8] = {sA.x, sA.y, sA.z, sA.w, sB.x, sB.y, sB.z, sB.w};
    int i0 = 0;
    float sx0 = sax[0], sx1 = sax[1];
#pragma unroll
    for (int j = 1; j <= 6; j++) {
        if (sax[j] <= x) { i0 = j; sx0 = sax[j]; sx1 = sax[j + 1]; }
    }
    float a = __fdividef(x - sx0, sx1 - sx0);

    // ---- fetch the two delay rows, pre-interpolate along slew axis ----
    const float4* dp = (const float4*)(dtab + arc * 64 + i0 * 8);
    float4 d0a = dp[0], d0b = dp[1], d1a = dp[2], d1b = dp[3];
    float dr0[8] = {d0a.x, d0a.y, d0a.z, d0a.w, d0b.x, d0b.y, d0b.z, d0b.w};
    float dr1[8] = {d1a.x, d1a.y, d1a.z, d1a.w, d1b.x, d1b.y, d1b.z, d1b.w};
    float dI[8];
#pragma unroll
    for (int j = 0; j < 8; j++) dI[j] = dr0[j] + a * (dr1[j] - dr0[j]);

    // ---- load axis ----
    const float4* cp = (const float4*)(lidx + arc * 8);
    float4 cA = cp[0], cB = cp[1];
    float cax[8] = {cA.x, cA.y, cA.z, cA.w, cB.x, cB.y, cB.z, cB.w};

    float inv_x = __fdividef(2.0f, fmaxf(x, 1e-30f));   // 2/in_slew, hoisted

    // ---- Ceff fixed-point iterations (all in registers) ----
    float ceff = fmaxf(c1f + c2f, 1e-30f);
#pragma unroll
    for (int it = 0; it < 3; it++) {
        float cx0 = cax[0], cx1 = cax[1], flo = dI[0], fhi = dI[1];
#pragma unroll
        for (int j = 1; j <= 6; j++) {
            bool p = cax[j] <= ceff;
            if (p) { cx0 = cax[j]; cx1 = cax[j + 1]; flo = dI[j]; fhi = dI[j + 1]; }
        }
        float b = __fdividef(ceff - cx0, cx1 - cx0);
        float d = flo + b * (fhi - flo);
        float tau = fmaxf(d, 1e-30f);
        float ratio = fminf(tau * inv_x, 10.0f);
        float h = (ratio > 0.01f)
                      ? __fdividef(1.0f - __expf(-ratio), ratio)
                      : 1.0f - 0.5f * ratio;
        ceff = fmaxf(c1f + c2f * h, 1e-30f);
    }
    float load = fminf(ceff, 1e-12f);   // MAX_CAP clamp

    // ---- slew rows, pre-interpolate ----
    const float4* ep = (const float4*)(stab + arc * 64 + i0 * 8);
    float4 e0a = ep[0], e0b = ep[1], e1a = ep[2], e1b = ep[3];
    float er0[8] = {e0a.x, e0a.y, e0a.z, e0a.w, e0b.x, e0b.y, e0b.z, e0b.w};
    float er1[8] = {e1a.x, e1a.y, e1a.z, e1a.w, e1b.x, e1b.y, e1b.z, e1b.w};
    float sI[8];
#pragma unroll
    for (int j = 0; j < 8; j++) sI[j] = er0[j] + a * (er1[j] - er0[j]);

    // ---- final bilinear eval at (x, load) ----
    float cx0 = cax[0], cx1 = cax[1];
    float flo = dI[0], fhi = dI[1];
    float glo = sI[0], ghi = sI[1];
#pragma unroll
    for (int j = 1; j <= 6; j++) {
        bool p = cax[j] <= load;
        if (p) {
            cx0 = cax[j]; cx1 = cax[j + 1];
            flo = dI[j]; fhi = dI[j + 1];
            glo = sI[j]; ghi = sI[j + 1];
        }
    }
    float b = __fdividef(load - cx0, cx1 - cx0);
    float arc_delay = flo + b * (fhi - flo);
    float arc_slew  = glo + b * (ghi - glo);

    out[t * 4 + k]     = arr + arc_delay;
    out[t * 4 + 2 + k] = arc_slew;
}

// ---------------- launch ------------------------------------------------------
extern "C" void kernel_launch(void* const* d_in, const int* in_sizes, int n_in,
                              void* d_out, int out_size) {
    const float* U_flat      = (const float*)d_in[0];
    const int*   gate_id     = (const int*)  d_in[1];
    const float* in_arr      = (const float*)d_in[2];
    const float* in_slew     = (const float*)d_in[3];
    const float* c1          = (const float*)d_in[4];
    const float* c2          = (const float*)d_in[5];
    // d_in[6] = rpi (unused by the math)
    const int*   arc_idx_r   = (const int*)  d_in[7];
    const int*   arc_idx_f   = (const int*)  d_in[8];
    const int*   unateness   = (const int*)  d_in[9];
    const float* delay_table = (const float*)d_in[10];
    const float* slew_table  = (const float*)d_in[11];
    const float* slew_index  = (const float*)d_in[12];
    const float* load_index  = (const float*)d_in[13];

    float* out     = (float*)d_out;               // [T,4] = 2M floats
    float* weights = (float*)d_out + 4 * TT;      // [TOTAL_U] = 1M floats

    // Main arc kernel (the big one)
    arcs_kernel<<<(2 * TT + 255) / 256, 256>>>(
        in_arr, in_slew, c1, c2, arc_idx_r, arc_idx_f, unateness,
        delay_table, slew_table, slew_index, load_index, out);

    // Segment softmax over sorted gate_id
    seg_bounds_kernel<<<(TOTAL_U + 255) / 256, 256>>>(gate_id);
    seg_reduce_kernel<<<(GG + 255) / 256, 256>>>(U_flat);
    seg_norm_kernel<<<(TOTAL_U + 255) / 256, 256>>>(U_flat, gate_id, weights);
}

// round 6
// speedup vs baseline: 1.0700x; 1.0700x over previous
#include <cuda_runtime.h>
#include <cstdint>

#define TT 500000
#define AA 20000
#define GG 250000
#define TOTAL_U 1000000

// ---------------- device-global scratch (allowed; zero-initialized at load) ---
__device__ float g_blk[AA * 7 * 32];   // per (arc,i0): [dr_i0(8), dr_i0+1(8), sr_i0(8), sr_i0+1(8)]
__device__ float g_meta[AA * 16];      // per arc: [sidx(8), lidx(8)]
__device__ int   g_start[GG];
__device__ int   g_end[GG];
__device__ float g_rsum[GG];

// ---------------- prep: repack LUTs into 128B blocks + 64B meta ---------------
__global__ void __launch_bounds__(256)
prep_kernel(const float* __restrict__ dtab, const float* __restrict__ stab,
            const float* __restrict__ sidx, const float* __restrict__ lidx) {
    int idx = blockIdx.x * blockDim.x + threadIdx.x;
    const int NBLK = AA * 7 * 32;                 // 4,480,000
    if (idx < NBLK) {
        int a = idx / 224;
        int r = idx - a * 224;
        int i = r >> 5;                           // i0 in 0..6
        int p = r & 31;                           // piece in 0..31
        const float* src = (p < 16) ? dtab : stab;
        int pp = p & 15;
        int row = i + (pp >> 3);                  // i0 or i0+1
        g_blk[idx] = src[a * 64 + row * 8 + (pp & 7)];
    } else {
        int m = idx - NBLK;
        if (m < AA * 16) {
            int a = m >> 4;
            int p = m & 15;
            g_meta[m] = (p < 8) ? sidx[a * 8 + p] : lidx[a * 8 + (p - 8)];
        }
    }
}

// ---------------- main timing-arc kernel: warp-cooperative gather -------------
// 128 threads/block, 4 warps. Each thread owns one arc-ref; each warp
// cooperatively loads its 32 refs' meta (64B) and table block (128B) with
// ~1 wavefront per ref, staged through conflict-free transposed smem.
__global__ void __launch_bounds__(128)
arcs_kernel(const float* __restrict__ in_arr,   // [T,2]
            const float* __restrict__ in_slew,  // [T,2]
            const float* __restrict__ c1,       // [T]
            const float* __restrict__ c2,       // [T]
            const int*   __restrict__ arc_r,    // [T]
            const int*   __restrict__ arc_f,    // [T]
            const int*   __restrict__ unate,    // [A]
            float* __restrict__ out)            // [T,4]
{
    __shared__ float meta_s[4][16 * 34];   // [piece][ref] stride 34 (bank-clean)
    __shared__ float blk_s[4][32 * 33];    // [piece][ref] stride 33 (bank-clean)

    int tid  = threadIdx.x;
    int warp = tid >> 5;
    int lane = tid & 31;
    float* ms = meta_s[warp];
    float* bs = blk_s[warp];

    int idx  = blockIdx.x * 128 + tid;
    int cidx = min(idx, 2 * TT - 1);             // clamp tail; stores guarded
    int k = (cidx >= TT) ? 1 : 0;
    int t = cidx - k * TT;

    int arc = k ? __ldg(arc_f + t) : __ldg(arc_r + t);
    int rf  = __ldg(unate + arc) ^ k;

    float x   = __ldg(in_slew + 2 * t + rf);
    float arr = __ldg(in_arr  + 2 * t + rf);
    float c1f = c1[t] * 1e-15f;
    float c2f = c2[t] * 1e-15f;

    // ---- cooperative meta load: 2 refs per iteration (16 lanes each) ----
    int half = lane >> 4;
    int p16  = lane & 15;
#pragma unroll
    for (int m = 0; m < 32; m += 2) {
        int aa  = __shfl_sync(0xffffffffu, arc, m + half);
        float v = g_meta[aa * 16 + p16];
        ms[p16 * 34 + (m + half)] = v;
    }
    __syncwarp();

    float sax[8], cax[8];
#pragma unroll
    for (int j = 0; j < 8; j++) sax[j] = ms[j * 34 + lane];
#pragma unroll
    for (int j = 0; j < 8; j++) cax[j] = ms[(j + 8) * 34 + lane];

    // ---- slew-axis interval ----
    int i0 = 0;
    float sx0 = sax[0], sx1 = sax[1];
#pragma unroll
    for (int j = 1; j <= 6; j++) {
        if (sax[j] <= x) { i0 = j; sx0 = sax[j]; sx1 = sax[j + 1]; }
    }
    float a = __fdividef(x - sx0, sx1 - sx0);

    // ---- cooperative 128B block load: 1 ref per iteration, 1 line each ----
    int blkbase = (arc * 7 + i0) * 32;
#pragma unroll
    for (int m = 0; m < 32; m++) {
        int bb  = __shfl_sync(0xffffffffu, blkbase, m);
        float v = g_blk[bb + lane];
        bs[lane * 33 + m] = v;
    }
    __syncwarp();

    // ---- read own block from smem, pre-interpolate along slew axis ----
    float dI[8], sI[8];
#pragma unroll
    for (int j = 0; j < 8; j++) {
        float d0 = bs[j * 33 + lane];
        float d1 = bs[(j + 8) * 33 + lane];
        dI[j] = d0 + a * (d1 - d0);
    }
#pragma unroll
    for (int j = 0; j < 8; j++) {
        float s0 = bs[(j + 16) * 33 + lane];
        float s1 = bs[(j + 24) * 33 + lane];
        sI[j] = s0 + a * (s1 - s0);
    }

    float inv_x = __fdividef(2.0f, fmaxf(x, 1e-30f));

    // ---- Ceff fixed-point iterations (registers only) ----
    float ceff = fmaxf(c1f + c2f, 1e-30f);
#pragma unroll
    for (int it = 0; it < 3; it++) {
        float cx0 = cax[0], cx1 = cax[1], flo = dI[0], fhi = dI[1];
#pragma unroll
        for (int j = 1; j <= 6; j++) {
            bool p = cax[j] <= ceff;
            if (p) { cx0 = cax[j]; cx1 = cax[j + 1]; flo = dI[j]; fhi = dI[j + 1]; }
        }
        float b = __fdividef(ceff - cx0, cx1 - cx0);
        float d = flo + b * (fhi - flo);
        float tau = fmaxf(d, 1e-30f);
        float ratio = fminf(tau * inv_x, 10.0f);
        float h = (ratio > 0.01f)
                      ? __fdividef(1.0f - __expf(-ratio), ratio)
                      : 1.0f - 0.5f * ratio;
        ceff = fmaxf(c1f + c2f * h, 1e-30f);
    }
    float load = fminf(ceff, 1e-12f);

    // ---- final bilinear eval at (x, load) ----
    float cx0 = cax[0], cx1 = cax[1];
    float flo = dI[0], fhi = dI[1];
    float glo = sI[0], ghi = sI[1];
#pragma unroll
    for (int j = 1; j <= 6; j++) {
        bool p = cax[j] <= load;
        if (p) {
            cx0 = cax[j]; cx1 = cax[j + 1];
            flo = dI[j]; fhi = dI[j + 1];
            glo = sI[j]; ghi = sI[j + 1];
        }
    }
    float b = __fdividef(load - cx0, cx1 - cx0);
    float arc_delay = flo + b * (fhi - flo);
    float arc_slew  = glo + b * (ghi - glo);

    if (idx < 2 * TT) {
        out[t * 4 + k]     = arr + arc_delay;
        out[t * 4 + 2 + k] = arc_slew;
    }
}

// ---------------- segment softmax (gate_id sorted; shift-invariant, no max) ---
__global__ void __launch_bounds__(256)
softmax_exp_bounds(const float* __restrict__ U, const int* __restrict__ gid,
                   float* __restrict__ w) {
    int i = blockIdx.x * blockDim.x + threadIdx.x;
    int b = i * 4;
    if (b >= TOTAL_U) return;
    float4 u = *(const float4*)(U + b);
    int4   g = *(const int4*)(gid + b);
    float4 e;
    e.x = __expf(u.x); e.y = __expf(u.y);
    e.z = __expf(u.z); e.w = __expf(u.w);
    *(float4*)(w + b) = e;

    int prev = (b == 0) ? -1 : __ldg(gid + b - 1);
    int nxt  = (b + 4 >= TOTAL_U) ? -1 : __ldg(gid + b + 4);
    if (g.x != prev) g_start[g.x] = b;
    if (g.y != g.x) { g_start[g.y] = b + 1; g_end[g.x] = b + 1; }
    if (g.z != g.y) { g_start[g.z] = b + 2; g_end[g.y] = b + 2; }
    if (g.w != g.z) { g_start[g.w] = b + 3; g_end[g.z] = b + 3; }
    if (nxt != g.w) g_end[g.w] = b + 4;
}

__global__ void __launch_bounds__(256)
softmax_segsum(const float* __restrict__ w) {
    int g = blockIdx.x * blockDim.x + threadIdx.x;
    if (g >= GG) return;
    int s = g_start[g], e = g_end[g];
    if (s >= e) return;                  // empty gate: never read downstream
    float sum = 0.f;
    for (int i = s; i < e; i++) sum += w[i];
    g_rsum[g] = __fdividef(1.f, sum);
}

__global__ void __launch_bounds__(256)
softmax_scale(const int* __restrict__ gid, float* __restrict__ w) {
    int i = blockIdx.x * blockDim.x + threadIdx.x;
    int b = i * 4;
    if (b >= TOTAL_U) return;
    int4   g = *(const int4*)(gid + b);
    float4 v = *(float4*)(w + b);
    v.x *= g_rsum[g.x];
    v.y *= g_rsum[g.y];
    v.z *= g_rsum[g.z];
    v.w *= g_rsum[g.w];
    *(float4*)(w + b) = v;
}

// ---------------- launch ------------------------------------------------------
extern "C" void kernel_launch(void* const* d_in, const int* in_sizes, int n_in,
                              void* d_out, int out_size) {
    const float* U_flat      = (const float*)d_in[0];
    const int*   gate_id     = (const int*)  d_in[1];
    const float* in_arr      = (const float*)d_in[2];
    const float* in_slew     = (const float*)d_in[3];
    const float* c1          = (const float*)d_in[4];
    const float* c2          = (const float*)d_in[5];
    // d_in[6] = rpi (unused by the math)
    const int*   arc_idx_r   = (const int*)  d_in[7];
    const int*   arc_idx_f   = (const int*)  d_in[8];
    const int*   unateness   = (const int*)  d_in[9];
    const float* delay_table = (const float*)d_in[10];
    const float* slew_table  = (const float*)d_in[11];
    const float* slew_index  = (const float*)d_in[12];
    const float* load_index  = (const float*)d_in[13];

    float* out     = (float*)d_out;               // [T,4] = 2M floats
    float* weights = (float*)d_out + 4 * TT;      // [TOTAL_U] = 1M floats

    // 1) repack LUTs (must precede arcs_kernel; same stream => ordered)
    const int NPREP = AA * 7 * 32 + AA * 16;      // 4.8M
    prep_kernel<<<(NPREP + 255) / 256, 256>>>(delay_table, slew_table,
                                              slew_index, load_index);

    // 2) main arc kernel (warp-cooperative gather)
    arcs_kernel<<<(2 * TT + 127) / 128, 128>>>(
        in_arr, in_slew, c1, c2, arc_idx_r, arc_idx_f, unateness, out);

    // 3) segment softmax over sorted gate_id
    softmax_exp_bounds<<<(TOTAL_U / 4 + 255) / 256, 256>>>(U_flat, gate_id, weights);
    softmax_segsum<<<(GG + 255) / 256, 256>>>(weights);
    softmax_scale<<<(TOTAL_U / 4 + 255) / 256, 256>>>(gate_id, weights);
}